// round 15
// baseline (speedup 1.0000x reference)
#include <cuda_runtime.h>
#include <cuda_bf16.h>
#include <cstdint>
#include <stdint.h>
#include <math.h>

// Problem constants (fixed by setup_inputs)
#define BB      2
#define SEQ     4096
#define DIM     2048
#define NH      16
#define DHALF   64          // Dh/2
#define DHEAD   128
#define NROWS   (BB*SEQ)    // 8192
#define NCHUNK  16
#define CHUNKL  256
#define F3      (3*DIM)     // 6144

// ---------------- scratch (device globals; no allocation allowed) ----------
__device__ float g_xn   [(size_t)NROWS * DIM];   // normed x
__device__ float g_fused[(size_t)NROWS * F3];    // dt|v|gate -> la|v_in|gate
__device__ float g_final[(size_t)NROWS * DIM];   // scan output
__device__ float g_bd   [BB * NCHUNK * DIM];
__device__ float g_bo   [BB * NCHUNK * DIM];
__device__ float g_carry[BB * NCHUNK * DIM];
// bf16 split operands for tensor-core GEMMs
__device__ __nv_bfloat16 g_a_hi [(size_t)NROWS * DIM];
__device__ __nv_bfloat16 g_a_lo [(size_t)NROWS * DIM];
__device__ __nv_bfloat16 g_b1_hi[(size_t)F3 * DIM];
__device__ __nv_bfloat16 g_b1_lo[(size_t)F3 * DIM];
__device__ __nv_bfloat16 g_b2_hi[(size_t)DIM * DIM];
__device__ __nv_bfloat16 g_b2_lo[(size_t)DIM * DIM];

// ---------------- baseline-ISA tensor-core helpers (sm_80-era, ok on sm_103)
__device__ __forceinline__ uint32_t smem_u32(const void* p) {
    uint32_t a;
    asm("{ .reg .u64 t; cvta.to.shared.u64 t, %1; cvt.u32.u64 %0, t; }"
        : "=r"(a) : "l"(p));
    return a;
}
__device__ __forceinline__ void ldm4(uint32_t* r, uint32_t addr) {
    asm volatile("ldmatrix.sync.aligned.m8n8.x4.shared.b16 {%0,%1,%2,%3}, [%4];"
        : "=r"(r[0]), "=r"(r[1]), "=r"(r[2]), "=r"(r[3]) : "r"(addr));
}
__device__ __forceinline__ void mma_bf16(float* c, const uint32_t* a,
                                         const uint32_t* b) {
    asm volatile(
        "mma.sync.aligned.m16n8k16.row.col.f32.bf16.bf16.f32 "
        "{%0,%1,%2,%3}, {%4,%5,%6,%7}, {%8,%9}, {%0,%1,%2,%3};"
        : "+f"(c[0]), "+f"(c[1]), "+f"(c[2]), "+f"(c[3])
        : "r"(a[0]), "r"(a[1]), "r"(a[2]), "r"(a[3]), "r"(b[0]), "r"(b[1]));
}
__device__ __forceinline__ void cp16(uint32_t sdst, const void* gsrc) {
    asm volatile("cp.async.cg.shared.global [%0], [%1], 16;"
                 :: "r"(sdst), "l"(gsrc));
}
#define CP_COMMIT() asm volatile("cp.async.commit_group;" ::: "memory")
#define CP_WAIT1()  asm volatile("cp.async.wait_group 1;" ::: "memory")
#define CP_WAIT0()  asm volatile("cp.async.wait_group 0;" ::: "memory")

// ---------------- mma.sync GEMM: C[M,N] = A[M,K]*B[N,K]^T (+Res) -----------
// BM=128, BN=256, BK=32, 8 warps (2m x 4n), warp tile 64x64, bf16 2-split:
// acc += Ah*Bh + Ah*Bl + Al*Bh. THREE-stage cp.async pipeline, one
// __syncthreads per K-tile. SMEM rows: 32 bf16 (64B data), stride 80B.
#define ATILE_B  10240            // 128 * 80
#define BTILE_B  20480            // 256 * 80
#define STAGE_B  (2 * ATILE_B + 2 * BTILE_B)   // 61440: Ah, Al, Bh, Bl
#define NSTAGE   3
#define SMEM_GEMM (NSTAGE * STAGE_B)           // 184320

__global__ __launch_bounds__(256, 1)
void k_gemm_mma(const __nv_bfloat16* __restrict__ Ah, const __nv_bfloat16* __restrict__ Al,
                const __nv_bfloat16* __restrict__ Bh, const __nv_bfloat16* __restrict__ Bl,
                float* __restrict__ C, const float* __restrict__ Res,
                int Nn, int Kn) {
    extern __shared__ char smem[];
    const uint32_t sbase = smem_u32(smem);
    const int tid  = threadIdx.x;
    const int wid  = tid >> 5;
    const int lane = tid & 31;
    const int wm   = wid & 1;        // 2 m-slices of 64
    const int wn   = wid >> 1;       // 4 n-slices of 64
    const int bx = blockIdx.x, by = blockIdx.y;

    const __nv_bfloat16* gpA[2];
    const __nv_bfloat16* gpB[2];
    gpA[0] = Ah + (size_t)(by * 128) * Kn;
    gpA[1] = Al + (size_t)(by * 128) * Kn;
    gpB[0] = Bh + (size_t)(bx * 256) * Kn;
    gpB[1] = Bl + (size_t)(bx * 256) * Kn;

    auto load_stage = [&](int stg, int k0) {
        uint32_t sb = sbase + stg * STAGE_B;
        #pragma unroll
        for (int t = 0; t < 2; t++) {           // Ah, Al: 512 chunks each
            uint32_t so = sb + t * ATILE_B;
            #pragma unroll
            for (int q = 0; q < 2; q++) {
                int l = tid + q * 256;
                int r = l >> 2, c = l & 3;
                cp16(so + r * 80 + c * 16, gpA[t] + (size_t)r * Kn + k0 + c * 8);
            }
        }
        #pragma unroll
        for (int t = 0; t < 2; t++) {           // Bh, Bl: 1024 chunks each
            uint32_t so = sb + 2 * ATILE_B + t * BTILE_B;
            #pragma unroll
            for (int q = 0; q < 4; q++) {
                int l = tid + q * 256;
                int r = l >> 2, c = l & 3;
                cp16(so + r * 80 + c * 16, gpB[t] + (size_t)r * Kn + k0 + c * 8);
            }
        }
        CP_COMMIT();
    };

    float acc[4][8][4];
    #pragma unroll
    for (int mi = 0; mi < 4; mi++)
        #pragma unroll
        for (int ni = 0; ni < 8; ni++)
            #pragma unroll
            for (int k = 0; k < 4; k++) acc[mi][ni][k] = 0.f;

    const int NT = Kn >> 5;          // K tiles of 32 (>= 2 here)
    load_stage(0, 0);
    load_stage(1, 32);

    for (int kt = 0; kt < NT; kt++) {
        if (kt + 1 < NT) CP_WAIT1(); else CP_WAIT0();
        __syncthreads();
        // stage (kt+2)%3 was last consumed at iter kt-1; all threads passed
        // the sync above after finishing that compute, so it is free now.
        if (kt + 2 < NT) load_stage((kt + 2) % NSTAGE, (kt + 2) * 32);

        const uint32_t sb = sbase + (kt % NSTAGE) * STAGE_B;
        #pragma unroll
        for (int ks = 0; ks < 2; ks++) {
            const int kc = ks * 16;
            uint32_t a_h[4][4], a_l[4][4], b_h[8][2], b_l[8][2];
            #pragma unroll
            for (int mi = 0; mi < 4; mi++) {
                int arow = wm * 64 + mi * 16 + (lane & 7) + ((lane >> 3) & 1) * 8;
                int acol = kc + ((lane >> 4) & 1) * 8;
                uint32_t ad = sb + arow * 80 + acol * 2;
                ldm4(a_h[mi], ad);
                ldm4(a_l[mi], ad + ATILE_B);
            }
            #pragma unroll
            for (int nj = 0; nj < 4; nj++) {
                int brow = wn * 64 + nj * 16 + (lane & 7) + ((lane >> 4) & 1) * 8;
                int bcol = kc + ((lane >> 3) & 1) * 8;
                uint32_t bd = sb + 2 * ATILE_B + brow * 80 + bcol * 2;
                uint32_t r[4];
                ldm4(r, bd);
                b_h[nj * 2][0] = r[0]; b_h[nj * 2][1] = r[1];
                b_h[nj * 2 + 1][0] = r[2]; b_h[nj * 2 + 1][1] = r[3];
                ldm4(r, bd + BTILE_B);
                b_l[nj * 2][0] = r[0]; b_l[nj * 2][1] = r[1];
                b_l[nj * 2 + 1][0] = r[2]; b_l[nj * 2 + 1][1] = r[3];
            }
            #pragma unroll
            for (int mi = 0; mi < 4; mi++)
                #pragma unroll
                for (int ni = 0; ni < 8; ni++) {
                    mma_bf16(acc[mi][ni], a_h[mi], b_h[ni]);
                    mma_bf16(acc[mi][ni], a_h[mi], b_l[ni]);
                    mma_bf16(acc[mi][ni], a_l[mi], b_h[ni]);
                }
        }
    }
    __syncthreads();

    // epilogue: frag (m16n8) rows g, g+8; cols (lane&3)*2
    #pragma unroll
    for (int mi = 0; mi < 4; mi++) {
        int gr = by * 128 + wm * 64 + mi * 16 + (lane >> 2);
        #pragma unroll
        for (int ni = 0; ni < 8; ni++) {
            int gc = bx * 256 + wn * 64 + ni * 8 + (lane & 3) * 2;
            float2 v0 = make_float2(acc[mi][ni][0], acc[mi][ni][1]);
            float2 v1 = make_float2(acc[mi][ni][2], acc[mi][ni][3]);
            if (Res) {
                float2 q0 = *(const float2*)(Res + (size_t)gr * Nn + gc);
                float2 q1 = *(const float2*)(Res + (size_t)(gr + 8) * Nn + gc);
                v0.x += q0.x; v0.y += q0.y; v1.x += q1.x; v1.y += q1.y;
            }
            *(float2*)(C + (size_t)gr * Nn + gc)       = v0;
            *(float2*)(C + (size_t)(gr + 8) * Nn + gc) = v1;
        }
    }
}

// ---------------- split fp32 -> bf16 hi/lo ---------------------------------
__global__ void k_split(const float* __restrict__ s,
                        __nv_bfloat16* __restrict__ hi,
                        __nv_bfloat16* __restrict__ lo, int n4) {
    int i = blockIdx.x * blockDim.x + threadIdx.x;
    if (i >= n4) return;
    float4 v = ((const float4*)s)[i];
    __nv_bfloat16 h0 = __float2bfloat16(v.x);
    __nv_bfloat16 h1 = __float2bfloat16(v.y);
    __nv_bfloat16 h2 = __float2bfloat16(v.z);
    __nv_bfloat16 h3 = __float2bfloat16(v.w);
    ((__nv_bfloat162*)hi)[2 * i + 0] = __halves2bfloat162(h0, h1);
    ((__nv_bfloat162*)hi)[2 * i + 1] = __halves2bfloat162(h2, h3);
    __nv_bfloat16 l0 = __float2bfloat16(v.x - __bfloat162float(h0));
    __nv_bfloat16 l1 = __float2bfloat16(v.y - __bfloat162float(h1));
    __nv_bfloat16 l2 = __float2bfloat16(v.z - __bfloat162float(h2));
    __nv_bfloat16 l3 = __float2bfloat16(v.w - __bfloat162float(h3));
    ((__nv_bfloat162*)lo)[2 * i + 0] = __halves2bfloat162(l0, l1);
    ((__nv_bfloat162*)lo)[2 * i + 1] = __halves2bfloat162(l2, l3);
}

// ---------------- 1. RMSNorm ------------------------------------------------
__global__ void k_rmsnorm(const float* __restrict__ x,
                          const float* __restrict__ scale) {
    int row = blockIdx.x;
    const float* xr = x + (size_t)row * DIM;
    float*       o  = g_xn + (size_t)row * DIM;

    float s = 0.f;
    for (int i = threadIdx.x; i < DIM; i += blockDim.x) {
        float v = xr[i];
        s += v * v;
    }
    __shared__ float red[32];
    #pragma unroll
    for (int off = 16; off; off >>= 1) s += __shfl_xor_sync(0xffffffffu, s, off);
    if ((threadIdx.x & 31) == 0) red[threadIdx.x >> 5] = s;
    __syncthreads();
    if (threadIdx.x < 32) {
        float t = (threadIdx.x < (blockDim.x >> 5)) ? red[threadIdx.x] : 0.f;
        #pragma unroll
        for (int off = 16; off; off >>= 1) t += __shfl_xor_sync(0xffffffffu, t, off);
        if (threadIdx.x == 0) red[0] = t;
    }
    __syncthreads();
    float rms = rsqrtf(red[0] / (float)DIM + 1e-6f);
    for (int i = threadIdx.x; i < DIM; i += blockDim.x) {
        float v = scale[i] * xr[i] * rms;
        o[i] = fminf(fmaxf(v, -60000.f), 60000.f);
    }
}

// ---------------- 2. depthwise conv + SiLU, emit bf16 hi/lo ----------------
__global__ void k_conv(const float* __restrict__ cw,
                       const float* __restrict__ cb) {
    int idx = blockIdx.x * blockDim.x + threadIdx.x;
    if (idx >= NROWS * DIM) return;
    int d   = idx & (DIM - 1);
    int row = idx >> 11;
    int n   = row & (SEQ - 1);

    const float4 w = *reinterpret_cast<const float4*>(&cw[d * 4]);
    float acc = cb[d];
    const float* base = g_xn + (size_t)row * DIM + d;
    if (n >= 3) {
        acc += w.x * base[-3 * DIM] + w.y * base[-2 * DIM]
             + w.z * base[-1 * DIM] + w.w * base[0];
    } else {
        if (n >= 2) acc += w.y * base[-2 * DIM];
        if (n >= 1) acc += w.z * base[-1 * DIM];
        acc += w.w * base[0];
    }
    float v = acc / (1.f + expf(-acc));
    __nv_bfloat16 h = __float2bfloat16(v);
    g_a_hi[idx] = h;
    g_a_lo[idx] = __float2bfloat16(v - __bfloat162float(h));
}

// ---------------- 4. dt/softplus, RoPE, gate (in place on g_fused) ---------
__global__ void k_post(const float* __restrict__ dt_bias) {
    int idx = blockIdx.x * blockDim.x + threadIdx.x;
    if (idx >= NROWS * NH * DHALF) return;
    int j   = idx & 63;
    int h   = (idx >> 6) & 15;
    int row = idx >> 10;
    int n   = row & (SEQ - 1);

    int d1 = h * DHEAD + j;
    int d2 = d1 + DHALF;
    float* fr = g_fused + (size_t)row * F3;

    float x1 = fr[d1] + dt_bias[d1];
    float x2 = fr[d2] + dt_bias[d2];
    float sp1 = fmaxf(x1, 0.f) + log1pf(expf(-fabsf(x1)));
    float sp2 = fmaxf(x2, 0.f) + log1pf(expf(-fabsf(x2)));
    float dt1 = fminf(fmaxf(sp1, 0.001f), 2.f);
    float dt2 = fminf(fmaxf(sp2, 0.001f), 2.f);
    fr[d1] = -dt1;
    fr[d2] = -dt2;

    float invf = powf(10000.0f, -(float)(2 * j) / 128.0f);
    float ang = (float)n * invf;
    float c = cosf(ang), s = sinf(ang);
    float v1 = fr[DIM + d1];
    float v2 = fr[DIM + d2];
    fr[DIM + d1] = (v1 * c - v2 * s) * dt1;
    fr[DIM + d2] = (v1 * s + v2 * c) * dt2;

    float g1 = fr[2 * DIM + d1];
    float g2 = fr[2 * DIM + d2];
    fr[2 * DIM + d1] = 1.f / (1.f + expf(-g1));
    fr[2 * DIM + d2] = 1.f / (1.f + expf(-g2));
}

// ---------------- 5. within-chunk scan -------------------------------------
__global__ void k_scan() {
    int idx = blockIdx.x * blockDim.x + threadIdx.x;
    if (idx >= BB * NCHUNK * DIM) return;
    int d  = idx & (DIM - 1);
    int nc = (idx >> 11) & (NCHUNK - 1);
    int b  = idx >> 15;

    size_t rowbase = (size_t)b * SEQ + nc * CHUNKL;
    const float* la = g_fused + rowbase * F3 + d;
    const float* vv = g_fused + rowbase * F3 + DIM + d;
    float*       ot = g_final + rowbase * DIM + d;

    float Ls = 0.f, Lmax = -1e30f;
    for (int i = 0; i < CHUNKL; i++) {
        Ls += la[(size_t)i * F3];
        float L = fminf(fmaxf(Ls, -20.f), 0.f);
        Lmax = fmaxf(Lmax, L);
    }
    Ls = 0.f;
    float sum = 0.f, lastL = 0.f, lastO = 0.f;
    for (int i = 0; i < CHUNKL; i++) {
        Ls += la[(size_t)i * F3];
        float L  = fminf(fmaxf(Ls, -20.f), 0.f);
        float Lt = L - Lmax;
        sum += expf(-Lt) * vv[(size_t)i * F3];
        float o = expf(Lt) * sum;
        ot[(size_t)i * DIM] = o;
        lastL = L; lastO = o;
    }
    g_bd[idx] = lastL;
    g_bo[idx] = lastO;
}

// ---------------- 6. cross-chunk carry scan --------------------------------
__global__ void k_carry() {
    int idx = blockIdx.x * blockDim.x + threadIdx.x;
    if (idx >= BB * DIM) return;
    int d = idx & (DIM - 1);
    int b = idx >> 11;

    float cd[NCHUNK];
    float run = 0.f, stab = -1e30f;
    #pragma unroll
    for (int nc = 0; nc < NCHUNK; nc++) {
        run += g_bd[(b * NCHUNK + nc) * DIM + d];
        float c = fminf(fmaxf(run, -80.f), 0.f);
        cd[nc] = c;
        stab = fmaxf(stab, c);
    }
    float acc = 0.f;
    #pragma unroll
    for (int nc = 0; nc < NCHUNK; nc++) {
        float ncd = fminf(fmaxf(cd[nc] - stab, -20.f), 0.f);
        g_carry[(b * NCHUNK + nc) * DIM + d] = acc * expf(ncd);
        acc += g_bo[(b * NCHUNK + nc) * DIM + d] * expf(-ncd);
    }
}

// ---------------- 7. apply carries: final += carry * exp(L) ----------------
__global__ void k_final() {
    int idx = blockIdx.x * blockDim.x + threadIdx.x;
    if (idx >= BB * NCHUNK * DIM) return;
    int d  = idx & (DIM - 1);
    int nc = (idx >> 11) & (NCHUNK - 1);
    int b  = idx >> 15;

    float carry = g_carry[idx];
    size_t rowbase = (size_t)b * SEQ + nc * CHUNKL;
    const float* la = g_fused + rowbase * F3 + d;
    float*       ot = g_final + rowbase * DIM + d;

    float Ls = 0.f;
    for (int i = 0; i < CHUNKL; i++) {
        Ls += la[(size_t)i * F3];
        float L = fminf(fmaxf(Ls, -20.f), 0.f);
        ot[(size_t)i * DIM] += carry * expf(L);
    }
}

// ---------------- 8. head mix + gate, emit bf16 hi/lo ----------------------
__global__ void k_mix(const float* __restrict__ head_mix) {
    int row = blockIdx.x;
    __shared__ float sf[DIM];
    __shared__ float hm[NH * NH];
    const float* fr = g_final + (size_t)row * DIM;
    const float* gr = g_fused + (size_t)row * F3 + 2 * DIM;

    for (int i = threadIdx.x; i < DIM; i += blockDim.x) sf[i] = fr[i];
    for (int i = threadIdx.x; i < NH * NH; i += blockDim.x) hm[i] = head_mix[i];
    __syncthreads();

    for (int i = threadIdx.x; i < DIM; i += blockDim.x) {
        int dd = i & (DHEAD - 1);
        int m  = i >> 7;
        float acc = 0.f;
        #pragma unroll
        for (int h = 0; h < NH; h++) acc += sf[h * DHEAD + dd] * hm[h * NH + m];
        float y = acc * gr[i];
        size_t o = (size_t)row * DIM + i;
        __nv_bfloat16 hv = __float2bfloat16(y);
        g_a_hi[o] = hv;
        g_a_lo[o] = __float2bfloat16(y - __bfloat162float(hv));
    }
}

// ---------------- launcher --------------------------------------------------
extern "C" void kernel_launch(void* const* d_in, const int* in_sizes, int n_in,
                              void* d_out, int out_size) {
    const float* x          = (const float*)d_in[0];
    const float* norm_scale = (const float*)d_in[1];
    const float* conv_w     = (const float*)d_in[2];
    const float* conv_b     = (const float*)d_in[3];
    const float* in_proj_w  = (const float*)d_in[4];
    const float* dt_bias    = (const float*)d_in[5];
    const float* head_mix   = (const float*)d_in[6];
    const float* out_proj_w = (const float*)d_in[7];
    float* out = (float*)d_out;

    float *p_fused;
    __nv_bfloat16 *p_ah, *p_al, *p_b1h, *p_b1l, *p_b2h, *p_b2l;
    cudaGetSymbolAddress((void**)&p_fused, g_fused);
    cudaGetSymbolAddress((void**)&p_ah,  g_a_hi);
    cudaGetSymbolAddress((void**)&p_al,  g_a_lo);
    cudaGetSymbolAddress((void**)&p_b1h, g_b1_hi);
    cudaGetSymbolAddress((void**)&p_b1l, g_b1_lo);
    cudaGetSymbolAddress((void**)&p_b2h, g_b2_hi);
    cudaGetSymbolAddress((void**)&p_b2l, g_b2_lo);

    cudaFuncSetAttribute(k_gemm_mma, cudaFuncAttributeMaxDynamicSharedMemorySize,
                         SMEM_GEMM);

    k_rmsnorm<<<NROWS, 256>>>(x, norm_scale);
    k_conv<<<(NROWS * DIM) / 256, 256>>>(conv_w, conv_b);
    k_split<<<(F3 * DIM / 4) / 256, 256>>>(in_proj_w, p_b1h, p_b1l, F3 * DIM / 4);
    k_split<<<(DIM * DIM / 4) / 256, 256>>>(out_proj_w, p_b2h, p_b2l, DIM * DIM / 4);

    // fused = xc @ in_proj_w^T : M=8192, N=6144, K=2048
    k_gemm_mma<<<dim3(F3 / 256, NROWS / 128), 256, SMEM_GEMM>>>(
        p_ah, p_al, p_b1h, p_b1l, p_fused, (const float*)0, F3, DIM);

    k_post<<<(NROWS * NH * DHALF) / 256, 256>>>(dt_bias);
    k_scan<<<(BB * NCHUNK * DIM) / 256, 256>>>();
    k_carry<<<(BB * DIM + 255) / 256, 256>>>();
    k_final<<<(BB * NCHUNK * DIM) / 256, 256>>>();
    k_mix<<<NROWS, 256>>>(head_mix);

    // out = residual + (vm*gate) @ out_proj_w^T : M=8192, N=2048, K=2048
    k_gemm_mma<<<dim3(DIM / 256, NROWS / 128), 256, SMEM_GEMM>>>(
        p_ah, p_al, p_b2h, p_b2l, out, x, DIM, DIM);
}

// round 16
// speedup vs baseline: 1.9031x; 1.9031x over previous
#include <cuda_runtime.h>
#include <cuda_bf16.h>
#include <cuda_fp16.h>
#include <cstdint>
#include <stdint.h>
#include <math.h>

// Problem constants (fixed by setup_inputs)
#define BB      2
#define SEQ     4096
#define DIM     2048
#define NH      16
#define DHALF   64          // Dh/2
#define DHEAD   128
#define NROWS   (BB*SEQ)    // 8192
#define NCHUNK  16
#define CHUNKL  256
#define F3      (3*DIM)     // 6144

// ---------------- scratch (device globals; no allocation allowed) ----------
__device__ float g_xn   [(size_t)NROWS * DIM];   // normed x
__device__ float g_fused[(size_t)NROWS * F3];    // dt|v|gate -> la|v_in|gate
__device__ float g_final[(size_t)NROWS * DIM];   // scan output
__device__ float g_bd   [BB * NCHUNK * DIM];
__device__ float g_bo   [BB * NCHUNK * DIM];
__device__ float g_carry[BB * NCHUNK * DIM];
// fp16 operands for tensor-core GEMMs (A single, B hi+lo split)
__device__ __half g_a16  [(size_t)NROWS * DIM];
__device__ __half g_b1_hi[(size_t)F3 * DIM];
__device__ __half g_b1_lo[(size_t)F3 * DIM];
__device__ __half g_b2_hi[(size_t)DIM * DIM];
__device__ __half g_b2_lo[(size_t)DIM * DIM];

// ---------------- baseline-ISA tensor-core helpers (sm_80-era, ok on sm_103)
__device__ __forceinline__ uint32_t smem_u32(const void* p) {
    uint32_t a;
    asm("{ .reg .u64 t; cvta.to.shared.u64 t, %1; cvt.u32.u64 %0, t; }"
        : "=r"(a) : "l"(p));
    return a;
}
__device__ __forceinline__ void ldm4(uint32_t* r, uint32_t addr) {
    asm volatile("ldmatrix.sync.aligned.m8n8.x4.shared.b16 {%0,%1,%2,%3}, [%4];"
        : "=r"(r[0]), "=r"(r[1]), "=r"(r[2]), "=r"(r[3]) : "r"(addr));
}
__device__ __forceinline__ void mma_f16(float* c, const uint32_t* a,
                                        const uint32_t* b) {
    asm volatile(
        "mma.sync.aligned.m16n8k16.row.col.f32.f16.f16.f32 "
        "{%0,%1,%2,%3}, {%4,%5,%6,%7}, {%8,%9}, {%0,%1,%2,%3};"
        : "+f"(c[0]), "+f"(c[1]), "+f"(c[2]), "+f"(c[3])
        : "r"(a[0]), "r"(a[1]), "r"(a[2]), "r"(a[3]), "r"(b[0]), "r"(b[1]));
}
__device__ __forceinline__ void cp16(uint32_t sdst, const void* gsrc) {
    asm volatile("cp.async.cg.shared.global [%0], [%1], 16;"
                 :: "r"(sdst), "l"(gsrc));
}
#define CP_COMMIT() asm volatile("cp.async.commit_group;" ::: "memory")
#define CP_WAIT1()  asm volatile("cp.async.wait_group 1;" ::: "memory")
#define CP_WAIT0()  asm volatile("cp.async.wait_group 0;" ::: "memory")

// ---------------- mma.sync GEMM: C[M,N] = A[M,K]*B[N,K]^T (+Res) -----------
// BM=BN=128, BK=32, 8 warps (2m x 4n), warp tile 64x32.
// fp16 asymmetric split: acc += A16*Bh + A16*Bl  (2 MMAs per product).
// THREE-stage cp.async pipeline, one __syncthreads per K-tile.
// SMEM tile: 128 rows x 32 fp16, row stride 80B (16B-aligned, bank-clean).
#define TILE_B   10240            // 128 * 80
#define STAGE_B  (3 * TILE_B)     // A16, Bh, Bl
#define NSTAGE   3
#define SMEM_GEMM (NSTAGE * STAGE_B)   // 92160

__global__ __launch_bounds__(256, 1)
void k_gemm_mma(const __half* __restrict__ A16,
                const __half* __restrict__ Bh, const __half* __restrict__ Bl,
                float* __restrict__ C, const float* __restrict__ Res,
                int Nn, int Kn) {
    extern __shared__ char smem[];
    const uint32_t sbase = smem_u32(smem);
    const int tid  = threadIdx.x;
    const int wid  = tid >> 5;
    const int lane = tid & 31;
    const int wm   = wid & 1;        // 2 m-slices of 64
    const int wn   = wid >> 1;       // 4 n-slices of 32
    const int bx = blockIdx.x, by = blockIdx.y;

    const __half* gp[3];
    gp[0] = A16 + (size_t)(by * 128) * Kn;
    gp[1] = Bh  + (size_t)(bx * 128) * Kn;
    gp[2] = Bl  + (size_t)(bx * 128) * Kn;

    // per-thread cp.async slots: 2 chunks per tile (512 chunks / 256 thr)
    const int r0 = tid >> 2;                 // rows for q=0 chunk
    const int c0 = tid & 3;                  // 16B sub-chunk
    const int r1 = (tid + 256) >> 2;
    const int c1 = (tid + 256) & 3;

    auto load_stage = [&](int stg, int k0) {
        uint32_t sb = sbase + stg * STAGE_B;
        #pragma unroll
        for (int t = 0; t < 3; t++) {
            cp16(sb + t * TILE_B + r0 * 80 + c0 * 16,
                 gp[t] + (size_t)r0 * Kn + k0 + c0 * 8);
            cp16(sb + t * TILE_B + r1 * 80 + c1 * 16,
                 gp[t] + (size_t)r1 * Kn + k0 + c1 * 8);
        }
        CP_COMMIT();
    };

    float acc[4][4][4];
    #pragma unroll
    for (int mi = 0; mi < 4; mi++)
        #pragma unroll
        for (int ni = 0; ni < 4; ni++)
            #pragma unroll
            for (int k = 0; k < 4; k++) acc[mi][ni][k] = 0.f;

    const int NT = Kn >> 5;          // K tiles of 32 (>= 2 here)
    load_stage(0, 0);
    load_stage(1, 32);

    for (int kt = 0; kt < NT; kt++) {
        if (kt + 1 < NT) CP_WAIT1(); else CP_WAIT0();
        __syncthreads();
        // stage (kt+2)%3 was last consumed at iter kt-1; all threads passed
        // the sync above after finishing that compute, so it is free now.
        if (kt + 2 < NT) load_stage((kt + 2) % NSTAGE, (kt + 2) * 32);

        const uint32_t sb = sbase + (kt % NSTAGE) * STAGE_B;
        #pragma unroll
        for (int ks = 0; ks < 2; ks++) {
            const int kc = ks * 16;
            uint32_t a16[4][4], b_h[4][2], b_l[4][2];
            #pragma unroll
            for (int mi = 0; mi < 4; mi++) {
                int arow = wm * 64 + mi * 16 + (lane & 7) + ((lane >> 3) & 1) * 8;
                int acol = kc + ((lane >> 4) & 1) * 8;
                ldm4(a16[mi], sb + arow * 80 + acol * 2);
            }
            #pragma unroll
            for (int nj = 0; nj < 2; nj++) {
                int brow = wn * 32 + nj * 16 + (lane & 7) + ((lane >> 4) & 1) * 8;
                int bcol = kc + ((lane >> 3) & 1) * 8;
                uint32_t bd = sb + TILE_B + brow * 80 + bcol * 2;
                uint32_t r[4];
                ldm4(r, bd);
                b_h[nj * 2][0] = r[0]; b_h[nj * 2][1] = r[1];
                b_h[nj * 2 + 1][0] = r[2]; b_h[nj * 2 + 1][1] = r[3];
                ldm4(r, bd + TILE_B);
                b_l[nj * 2][0] = r[0]; b_l[nj * 2][1] = r[1];
                b_l[nj * 2 + 1][0] = r[2]; b_l[nj * 2 + 1][1] = r[3];
            }
            #pragma unroll
            for (int mi = 0; mi < 4; mi++)
                #pragma unroll
                for (int ni = 0; ni < 4; ni++) {
                    mma_f16(acc[mi][ni], a16[mi], b_h[ni]);
                    mma_f16(acc[mi][ni], a16[mi], b_l[ni]);
                }
        }
    }
    __syncthreads();

    // epilogue: frag (m16n8) rows g, g+8; cols (lane&3)*2
    #pragma unroll
    for (int mi = 0; mi < 4; mi++) {
        int gr = by * 128 + wm * 64 + mi * 16 + (lane >> 2);
        #pragma unroll
        for (int ni = 0; ni < 4; ni++) {
            int gc = bx * 128 + wn * 32 + ni * 8 + (lane & 3) * 2;
            float2 v0 = make_float2(acc[mi][ni][0], acc[mi][ni][1]);
            float2 v1 = make_float2(acc[mi][ni][2], acc[mi][ni][3]);
            if (Res) {
                float2 q0 = *(const float2*)(Res + (size_t)gr * Nn + gc);
                float2 q1 = *(const float2*)(Res + (size_t)(gr + 8) * Nn + gc);
                v0.x += q0.x; v0.y += q0.y; v1.x += q1.x; v1.y += q1.y;
            }
            *(float2*)(C + (size_t)gr * Nn + gc)       = v0;
            *(float2*)(C + (size_t)(gr + 8) * Nn + gc) = v1;
        }
    }
}

// ---------------- split fp32 -> fp16 hi/lo (weights) -----------------------
__global__ void k_split(const float* __restrict__ s,
                        __half* __restrict__ hi,
                        __half* __restrict__ lo, int n4) {
    int i = blockIdx.x * blockDim.x + threadIdx.x;
    if (i >= n4) return;
    float4 v = ((const float4*)s)[i];
    __half h0 = __float2half_rn(v.x);
    __half h1 = __float2half_rn(v.y);
    __half h2 = __float2half_rn(v.z);
    __half h3 = __float2half_rn(v.w);
    ((__half2*)hi)[2 * i + 0] = __halves2half2(h0, h1);
    ((__half2*)hi)[2 * i + 1] = __halves2half2(h2, h3);
    __half l0 = __float2half_rn(v.x - __half2float(h0));
    __half l1 = __float2half_rn(v.y - __half2float(h1));
    __half l2 = __float2half_rn(v.z - __half2float(h2));
    __half l3 = __float2half_rn(v.w - __half2float(h3));
    ((__half2*)lo)[2 * i + 0] = __halves2half2(l0, l1);
    ((__half2*)lo)[2 * i + 1] = __halves2half2(l2, l3);
}

// ---------------- 1. RMSNorm ------------------------------------------------
__global__ void k_rmsnorm(const float* __restrict__ x,
                          const float* __restrict__ scale) {
    int row = blockIdx.x;
    const float* xr = x + (size_t)row * DIM;
    float*       o  = g_xn + (size_t)row * DIM;

    float s = 0.f;
    for (int i = threadIdx.x; i < DIM; i += blockDim.x) {
        float v = xr[i];
        s += v * v;
    }
    __shared__ float red[32];
    #pragma unroll
    for (int off = 16; off; off >>= 1) s += __shfl_xor_sync(0xffffffffu, s, off);
    if ((threadIdx.x & 31) == 0) red[threadIdx.x >> 5] = s;
    __syncthreads();
    if (threadIdx.x < 32) {
        float t = (threadIdx.x < (blockDim.x >> 5)) ? red[threadIdx.x] : 0.f;
        #pragma unroll
        for (int off = 16; off; off >>= 1) t += __shfl_xor_sync(0xffffffffu, t, off);
        if (threadIdx.x == 0) red[0] = t;
    }
    __syncthreads();
    float rms = rsqrtf(red[0] / (float)DIM + 1e-6f);
    for (int i = threadIdx.x; i < DIM; i += blockDim.x) {
        float v = scale[i] * xr[i] * rms;
        o[i] = fminf(fmaxf(v, -60000.f), 60000.f);
    }
}

// ---------------- 2. depthwise conv + SiLU, emit fp16 A --------------------
__global__ void k_conv(const float* __restrict__ cw,
                       const float* __restrict__ cb) {
    int idx = blockIdx.x * blockDim.x + threadIdx.x;
    if (idx >= NROWS * DIM) return;
    int d   = idx & (DIM - 1);
    int row = idx >> 11;
    int n   = row & (SEQ - 1);

    const float4 w = *reinterpret_cast<const float4*>(&cw[d * 4]);
    float acc = cb[d];
    const float* base = g_xn + (size_t)row * DIM + d;
    if (n >= 3) {
        acc += w.x * base[-3 * DIM] + w.y * base[-2 * DIM]
             + w.z * base[-1 * DIM] + w.w * base[0];
    } else {
        if (n >= 2) acc += w.y * base[-2 * DIM];
        if (n >= 1) acc += w.z * base[-1 * DIM];
        acc += w.w * base[0];
    }
    float v = acc / (1.f + expf(-acc));
    g_a16[idx] = __float2half_rn(v);
}

// ---------------- 4. dt/softplus, RoPE, gate (in place on g_fused) ---------
__global__ void k_post(const float* __restrict__ dt_bias) {
    int idx = blockIdx.x * blockDim.x + threadIdx.x;
    if (idx >= NROWS * NH * DHALF) return;
    int j   = idx & 63;
    int h   = (idx >> 6) & 15;
    int row = idx >> 10;
    int n   = row & (SEQ - 1);

    int d1 = h * DHEAD + j;
    int d2 = d1 + DHALF;
    float* fr = g_fused + (size_t)row * F3;

    float x1 = fr[d1] + dt_bias[d1];
    float x2 = fr[d2] + dt_bias[d2];
    float sp1 = fmaxf(x1, 0.f) + log1pf(expf(-fabsf(x1)));
    float sp2 = fmaxf(x2, 0.f) + log1pf(expf(-fabsf(x2)));
    float dt1 = fminf(fmaxf(sp1, 0.001f), 2.f);
    float dt2 = fminf(fmaxf(sp2, 0.001f), 2.f);
    fr[d1] = -dt1;
    fr[d2] = -dt2;

    float invf = powf(10000.0f, -(float)(2 * j) / 128.0f);
    float ang = (float)n * invf;
    float c = cosf(ang), s = sinf(ang);
    float v1 = fr[DIM + d1];
    float v2 = fr[DIM + d2];
    fr[DIM + d1] = (v1 * c - v2 * s) * dt1;
    fr[DIM + d2] = (v1 * s + v2 * c) * dt2;

    float g1 = fr[2 * DIM + d1];
    float g2 = fr[2 * DIM + d2];
    fr[2 * DIM + d1] = 1.f / (1.f + expf(-g1));
    fr[2 * DIM + d2] = 1.f / (1.f + expf(-g2));
}

// ---------------- 5. within-chunk scan -------------------------------------
__global__ void k_scan() {
    int idx = blockIdx.x * blockDim.x + threadIdx.x;
    if (idx >= BB * NCHUNK * DIM) return;
    int d  = idx & (DIM - 1);
    int nc = (idx >> 11) & (NCHUNK - 1);
    int b  = idx >> 15;

    size_t rowbase = (size_t)b * SEQ + nc * CHUNKL;
    const float* la = g_fused + rowbase * F3 + d;
    const float* vv = g_fused + rowbase * F3 + DIM + d;
    float*       ot = g_final + rowbase * DIM + d;

    float Ls = 0.f, Lmax = -1e30f;
    for (int i = 0; i < CHUNKL; i++) {
        Ls += la[(size_t)i * F3];
        float L = fminf(fmaxf(Ls, -20.f), 0.f);
        Lmax = fmaxf(Lmax, L);
    }
    Ls = 0.f;
    float sum = 0.f, lastL = 0.f, lastO = 0.f;
    for (int i = 0; i < CHUNKL; i++) {
        Ls += la[(size_t)i * F3];
        float L  = fminf(fmaxf(Ls, -20.f), 0.f);
        float Lt = L - Lmax;
        sum += expf(-Lt) * vv[(size_t)i * F3];
        float o = expf(Lt) * sum;
        ot[(size_t)i * DIM] = o;
        lastL = L; lastO = o;
    }
    g_bd[idx] = lastL;
    g_bo[idx] = lastO;
}

// ---------------- 6. cross-chunk carry scan --------------------------------
__global__ void k_carry() {
    int idx = blockIdx.x * blockDim.x + threadIdx.x;
    if (idx >= BB * DIM) return;
    int d = idx & (DIM - 1);
    int b = idx >> 11;

    float cd[NCHUNK];
    float run = 0.f, stab = -1e30f;
    #pragma unroll
    for (int nc = 0; nc < NCHUNK; nc++) {
        run += g_bd[(b * NCHUNK + nc) * DIM + d];
        float c = fminf(fmaxf(run, -80.f), 0.f);
        cd[nc] = c;
        stab = fmaxf(stab, c);
    }
    float acc = 0.f;
    #pragma unroll
    for (int nc = 0; nc < NCHUNK; nc++) {
        float ncd = fminf(fmaxf(cd[nc] - stab, -20.f), 0.f);
        g_carry[(b * NCHUNK + nc) * DIM + d] = acc * expf(ncd);
        acc += g_bo[(b * NCHUNK + nc) * DIM + d] * expf(-ncd);
    }
}

// ---------------- 7. apply carries: final += carry * exp(L) ----------------
__global__ void k_final() {
    int idx = blockIdx.x * blockDim.x + threadIdx.x;
    if (idx >= BB * NCHUNK * DIM) return;
    int d  = idx & (DIM - 1);
    int nc = (idx >> 11) & (NCHUNK - 1);
    int b  = idx >> 15;

    float carry = g_carry[idx];
    size_t rowbase = (size_t)b * SEQ + nc * CHUNKL;
    const float* la = g_fused + rowbase * F3 + d;
    float*       ot = g_final + rowbase * DIM + d;

    float Ls = 0.f;
    for (int i = 0; i < CHUNKL; i++) {
        Ls += la[(size_t)i * F3];
        float L = fminf(fmaxf(Ls, -20.f), 0.f);
        ot[(size_t)i * DIM] += carry * expf(L);
    }
}

// ---------------- 8. head mix + gate, emit fp16 A --------------------------
__global__ void k_mix(const float* __restrict__ head_mix) {
    int row = blockIdx.x;
    __shared__ float sf[DIM];
    __shared__ float hm[NH * NH];
    const float* fr = g_final + (size_t)row * DIM;
    const float* gr = g_fused + (size_t)row * F3 + 2 * DIM;

    for (int i = threadIdx.x; i < DIM; i += blockDim.x) sf[i] = fr[i];
    for (int i = threadIdx.x; i < NH * NH; i += blockDim.x) hm[i] = head_mix[i];
    __syncthreads();

    for (int i = threadIdx.x; i < DIM; i += blockDim.x) {
        int dd = i & (DHEAD - 1);
        int m  = i >> 7;
        float acc = 0.f;
        #pragma unroll
        for (int h = 0; h < NH; h++) acc += sf[h * DHEAD + dd] * hm[h * NH + m];
        float y = acc * gr[i];
        g_a16[(size_t)row * DIM + i] = __float2half_rn(y);
    }
}

// ---------------- launcher --------------------------------------------------
extern "C" void kernel_launch(void* const* d_in, const int* in_sizes, int n_in,
                              void* d_out, int out_size) {
    const float* x          = (const float*)d_in[0];
    const float* norm_scale = (const float*)d_in[1];
    const float* conv_w     = (const float*)d_in[2];
    const float* conv_b     = (const float*)d_in[3];
    const float* in_proj_w  = (const float*)d_in[4];
    const float* dt_bias    = (const float*)d_in[5];
    const float* head_mix   = (const float*)d_in[6];
    const float* out_proj_w = (const float*)d_in[7];
    float* out = (float*)d_out;

    float *p_fused;
    __half *p_a16, *p_b1h, *p_b1l, *p_b2h, *p_b2l;
    cudaGetSymbolAddress((void**)&p_fused, g_fused);
    cudaGetSymbolAddress((void**)&p_a16, g_a16);
    cudaGetSymbolAddress((void**)&p_b1h, g_b1_hi);
    cudaGetSymbolAddress((void**)&p_b1l, g_b1_lo);
    cudaGetSymbolAddress((void**)&p_b2h, g_b2_hi);
    cudaGetSymbolAddress((void**)&p_b2l, g_b2_lo);

    cudaFuncSetAttribute(k_gemm_mma, cudaFuncAttributeMaxDynamicSharedMemorySize,
                         SMEM_GEMM);

    k_rmsnorm<<<NROWS, 256>>>(x, norm_scale);
    k_conv<<<(NROWS * DIM) / 256, 256>>>(conv_w, conv_b);
    k_split<<<(F3 * DIM / 4) / 256, 256>>>(in_proj_w, p_b1h, p_b1l, F3 * DIM / 4);
    k_split<<<(DIM * DIM / 4) / 256, 256>>>(out_proj_w, p_b2h, p_b2l, DIM * DIM / 4);

    // fused = xc @ in_proj_w^T : M=8192, N=6144, K=2048
    k_gemm_mma<<<dim3(F3 / 128, NROWS / 128), 256, SMEM_GEMM>>>(
        p_a16, p_b1h, p_b1l, p_fused, (const float*)0, F3, DIM);

    k_post<<<(NROWS * NH * DHALF) / 256, 256>>>(dt_bias);
    k_scan<<<(BB * NCHUNK * DIM) / 256, 256>>>();
    k_carry<<<(BB * DIM + 255) / 256, 256>>>();
    k_final<<<(BB * NCHUNK * DIM) / 256, 256>>>();
    k_mix<<<NROWS, 256>>>(head_mix);

    // out = residual + (vm*gate) @ out_proj_w^T : M=8192, N=2048, K=2048
    k_gemm_mma<<<dim3(DIM / 128, NROWS / 128), 256, SMEM_GEMM>>>(
        p_a16, p_b2h, p_b2l, out, x, DIM, DIM);
}

// round 17
// speedup vs baseline: 2.5798x; 1.3556x over previous
#include <cuda_runtime.h>
#include <cuda_bf16.h>
#include <cuda_fp16.h>
#include <cstdint>
#include <stdint.h>
#include <math.h>

// Problem constants (fixed by setup_inputs)
#define BB      2
#define SEQ     4096
#define DIM     2048
#define NH      16
#define DHALF   64          // Dh/2
#define DHEAD   128
#define NROWS   (BB*SEQ)    // 8192
#define NCHUNK  16
#define CHUNKL  256
#define F3      (3*DIM)     // 6144

// ---------------- scratch (device globals; no allocation allowed) ----------
__device__ float g_xn   [(size_t)NROWS * DIM];   // normed x
__device__ float g_fused[(size_t)NROWS * F3];    // dt|v|gate -> la|v_in|gate
__device__ float g_final[(size_t)NROWS * DIM];   // scan output
__device__ float g_bd   [BB * NCHUNK * DIM];
__device__ float g_bo   [BB * NCHUNK * DIM];
__device__ float g_carry[BB * NCHUNK * DIM];
// fp16 operands for tensor-core GEMMs (single precision-level, no split)
__device__ __half g_a16  [(size_t)NROWS * DIM];
__device__ __half g_b1_16[(size_t)F3 * DIM];
__device__ __half g_b2_16[(size_t)DIM * DIM];

// ---------------- baseline-ISA tensor-core helpers (sm_80-era, ok on sm_103)
__device__ __forceinline__ uint32_t smem_u32(const void* p) {
    uint32_t a;
    asm("{ .reg .u64 t; cvta.to.shared.u64 t, %1; cvt.u32.u64 %0, t; }"
        : "=r"(a) : "l"(p));
    return a;
}
__device__ __forceinline__ void ldm4(uint32_t* r, uint32_t addr) {
    asm volatile("ldmatrix.sync.aligned.m8n8.x4.shared.b16 {%0,%1,%2,%3}, [%4];"
        : "=r"(r[0]), "=r"(r[1]), "=r"(r[2]), "=r"(r[3]) : "r"(addr));
}
__device__ __forceinline__ void mma_f16(float* c, const uint32_t* a,
                                        const uint32_t* b) {
    asm volatile(
        "mma.sync.aligned.m16n8k16.row.col.f32.f16.f16.f32 "
        "{%0,%1,%2,%3}, {%4,%5,%6,%7}, {%8,%9}, {%0,%1,%2,%3};"
        : "+f"(c[0]), "+f"(c[1]), "+f"(c[2]), "+f"(c[3])
        : "r"(a[0]), "r"(a[1]), "r"(a[2]), "r"(a[3]), "r"(b[0]), "r"(b[1]));
}
__device__ __forceinline__ void cp16(uint32_t sdst, const void* gsrc) {
    asm volatile("cp.async.cg.shared.global [%0], [%1], 16;"
                 :: "r"(sdst), "l"(gsrc));
}
#define CP_COMMIT() asm volatile("cp.async.commit_group;" ::: "memory")
#define CP_WAIT1()  asm volatile("cp.async.wait_group 1;" ::: "memory")
#define CP_WAIT0()  asm volatile("cp.async.wait_group 0;" ::: "memory")

// ---------------- mma.sync GEMM: C[M,N] = A[M,K]*B[N,K]^T (+Res) -----------
// BM=BN=128, BK=32, 8 warps (2m x 4n), warp tile 64x32.
// Plain fp16: acc += A16*B16  (1 MMA per product).
// THREE-stage cp.async pipeline, one __syncthreads per K-tile.
// SMEM tile: 128 rows x 32 fp16, row stride 80B (16B-aligned, bank-clean).
#define TILE_B   10240            // 128 * 80
#define STAGE_B  (2 * TILE_B)     // A16, B16
#define NSTAGE   3
#define SMEM_GEMM (NSTAGE * STAGE_B)   // 61440

__global__ __launch_bounds__(256, 1)
void k_gemm_mma(const __half* __restrict__ A16, const __half* __restrict__ B16,
                float* __restrict__ C, const float* __restrict__ Res,
                int Nn, int Kn) {
    extern __shared__ char smem[];
    const uint32_t sbase = smem_u32(smem);
    const int tid  = threadIdx.x;
    const int wid  = tid >> 5;
    const int lane = tid & 31;
    const int wm   = wid & 1;        // 2 m-slices of 64
    const int wn   = wid >> 1;       // 4 n-slices of 32
    const int bx = blockIdx.x, by = blockIdx.y;

    const __half* gp[2];
    gp[0] = A16 + (size_t)(by * 128) * Kn;
    gp[1] = B16 + (size_t)(bx * 128) * Kn;

    // per-thread cp.async slots: 2 chunks per tile (512 chunks / 256 thr)
    const int r0 = tid >> 2;                 // rows for q=0 chunk
    const int c0 = tid & 3;                  // 16B sub-chunk
    const int r1 = (tid + 256) >> 2;
    const int c1 = (tid + 256) & 3;

    auto load_stage = [&](int stg, int k0) {
        uint32_t sb = sbase + stg * STAGE_B;
        #pragma unroll
        for (int t = 0; t < 2; t++) {
            cp16(sb + t * TILE_B + r0 * 80 + c0 * 16,
                 gp[t] + (size_t)r0 * Kn + k0 + c0 * 8);
            cp16(sb + t * TILE_B + r1 * 80 + c1 * 16,
                 gp[t] + (size_t)r1 * Kn + k0 + c1 * 8);
        }
        CP_COMMIT();
    };

    float acc[4][4][4];
    #pragma unroll
    for (int mi = 0; mi < 4; mi++)
        #pragma unroll
        for (int ni = 0; ni < 4; ni++)
            #pragma unroll
            for (int k = 0; k < 4; k++) acc[mi][ni][k] = 0.f;

    const int NT = Kn >> 5;          // K tiles of 32 (>= 2 here)
    load_stage(0, 0);
    load_stage(1, 32);

    for (int kt = 0; kt < NT; kt++) {
        if (kt + 1 < NT) CP_WAIT1(); else CP_WAIT0();
        __syncthreads();
        // stage (kt+2)%3 was last consumed at iter kt-1; all threads passed
        // the sync above after finishing that compute, so it is free now.
        if (kt + 2 < NT) load_stage((kt + 2) % NSTAGE, (kt + 2) * 32);

        const uint32_t sb = sbase + (kt % NSTAGE) * STAGE_B;
        #pragma unroll
        for (int ks = 0; ks < 2; ks++) {
            const int kc = ks * 16;
            uint32_t a16[4][4], bf[4][2];
            #pragma unroll
            for (int mi = 0; mi < 4; mi++) {
                int arow = wm * 64 + mi * 16 + (lane & 7) + ((lane >> 3) & 1) * 8;
                int acol = kc + ((lane >> 4) & 1) * 8;
                ldm4(a16[mi], sb + arow * 80 + acol * 2);
            }
            #pragma unroll
            for (int nj = 0; nj < 2; nj++) {
                int brow = wn * 32 + nj * 16 + (lane & 7) + ((lane >> 4) & 1) * 8;
                int bcol = kc + ((lane >> 3) & 1) * 8;
                uint32_t r[4];
                ldm4(r, sb + TILE_B + brow * 80 + bcol * 2);
                bf[nj * 2][0] = r[0]; bf[nj * 2][1] = r[1];
                bf[nj * 2 + 1][0] = r[2]; bf[nj * 2 + 1][1] = r[3];
            }
            #pragma unroll
            for (int mi = 0; mi < 4; mi++)
                #pragma unroll
                for (int ni = 0; ni < 4; ni++)
                    mma_f16(acc[mi][ni], a16[mi], bf[ni]);
        }
    }
    __syncthreads();

    // epilogue: frag (m16n8) rows g, g+8; cols (lane&3)*2
    #pragma unroll
    for (int mi = 0; mi < 4; mi++) {
        int gr = by * 128 + wm * 64 + mi * 16 + (lane >> 2);
        #pragma unroll
        for (int ni = 0; ni < 4; ni++) {
            int gc = bx * 128 + wn * 32 + ni * 8 + (lane & 3) * 2;
            float2 v0 = make_float2(acc[mi][ni][0], acc[mi][ni][1]);
            float2 v1 = make_float2(acc[mi][ni][2], acc[mi][ni][3]);
            if (Res) {
                float2 q0 = *(const float2*)(Res + (size_t)gr * Nn + gc);
                float2 q1 = *(const float2*)(Res + (size_t)(gr + 8) * Nn + gc);
                v0.x += q0.x; v0.y += q0.y; v1.x += q1.x; v1.y += q1.y;
            }
            *(float2*)(C + (size_t)gr * Nn + gc)       = v0;
            *(float2*)(C + (size_t)(gr + 8) * Nn + gc) = v1;
        }
    }
}

// ---------------- convert fp32 -> fp16 (weights) ---------------------------
__global__ void k_cvt16(const float* __restrict__ s,
                        __half* __restrict__ o, int n4) {
    int i = blockIdx.x * blockDim.x + threadIdx.x;
    if (i >= n4) return;
    float4 v = ((const float4*)s)[i];
    ((__half2*)o)[2 * i + 0] = __halves2half2(__float2half_rn(v.x), __float2half_rn(v.y));
    ((__half2*)o)[2 * i + 1] = __halves2half2(__float2half_rn(v.z), __float2half_rn(v.w));
}

// ---------------- 1. RMSNorm ------------------------------------------------
__global__ void k_rmsnorm(const float* __restrict__ x,
                          const float* __restrict__ scale) {
    int row = blockIdx.x;
    const float* xr = x + (size_t)row * DIM;
    float*       o  = g_xn + (size_t)row * DIM;

    float s = 0.f;
    for (int i = threadIdx.x; i < DIM; i += blockDim.x) {
        float v = xr[i];
        s += v * v;
    }
    __shared__ float red[32];
    #pragma unroll
    for (int off = 16; off; off >>= 1) s += __shfl_xor_sync(0xffffffffu, s, off);
    if ((threadIdx.x & 31) == 0) red[threadIdx.x >> 5] = s;
    __syncthreads();
    if (threadIdx.x < 32) {
        float t = (threadIdx.x < (blockDim.x >> 5)) ? red[threadIdx.x] : 0.f;
        #pragma unroll
        for (int off = 16; off; off >>= 1) t += __shfl_xor_sync(0xffffffffu, t, off);
        if (threadIdx.x == 0) red[0] = t;
    }
    __syncthreads();
    float rms = rsqrtf(red[0] / (float)DIM + 1e-6f);
    for (int i = threadIdx.x; i < DIM; i += blockDim.x) {
        float v = scale[i] * xr[i] * rms;
        o[i] = fminf(fmaxf(v, -60000.f), 60000.f);
    }
}

// ---------------- 2. depthwise conv + SiLU, emit fp16 A --------------------
__global__ void k_conv(const float* __restrict__ cw,
                       const float* __restrict__ cb) {
    int idx = blockIdx.x * blockDim.x + threadIdx.x;
    if (idx >= NROWS * DIM) return;
    int d   = idx & (DIM - 1);
    int row = idx >> 11;
    int n   = row & (SEQ - 1);

    const float4 w = *reinterpret_cast<const float4*>(&cw[d * 4]);
    float acc = cb[d];
    const float* base = g_xn + (size_t)row * DIM + d;
    if (n >= 3) {
        acc += w.x * base[-3 * DIM] + w.y * base[-2 * DIM]
             + w.z * base[-1 * DIM] + w.w * base[0];
    } else {
        if (n >= 2) acc += w.y * base[-2 * DIM];
        if (n >= 1) acc += w.z * base[-1 * DIM];
        acc += w.w * base[0];
    }
    float v = acc / (1.f + expf(-acc));
    g_a16[idx] = __float2half_rn(v);
}

// ---------------- 4. dt/softplus, RoPE, gate (in place on g_fused) ---------
__global__ void k_post(const float* __restrict__ dt_bias) {
    int idx = blockIdx.x * blockDim.x + threadIdx.x;
    if (idx >= NROWS * NH * DHALF) return;
    int j   = idx & 63;
    int h   = (idx >> 6) & 15;
    int row = idx >> 10;
    int n   = row & (SEQ - 1);

    int d1 = h * DHEAD + j;
    int d2 = d1 + DHALF;
    float* fr = g_fused + (size_t)row * F3;

    float x1 = fr[d1] + dt_bias[d1];
    float x2 = fr[d2] + dt_bias[d2];
    float sp1 = fmaxf(x1, 0.f) + log1pf(expf(-fabsf(x1)));
    float sp2 = fmaxf(x2, 0.f) + log1pf(expf(-fabsf(x2)));
    float dt1 = fminf(fmaxf(sp1, 0.001f), 2.f);
    float dt2 = fminf(fmaxf(sp2, 0.001f), 2.f);
    fr[d1] = -dt1;
    fr[d2] = -dt2;

    float invf = powf(10000.0f, -(float)(2 * j) / 128.0f);
    float ang = (float)n * invf;
    float c = cosf(ang), s = sinf(ang);
    float v1 = fr[DIM + d1];
    float v2 = fr[DIM + d2];
    fr[DIM + d1] = (v1 * c - v2 * s) * dt1;
    fr[DIM + d2] = (v1 * s + v2 * c) * dt2;

    float g1 = fr[2 * DIM + d1];
    float g2 = fr[2 * DIM + d2];
    fr[2 * DIM + d1] = 1.f / (1.f + expf(-g1));
    fr[2 * DIM + d2] = 1.f / (1.f + expf(-g2));
}

// ---------------- 5. within-chunk scan -------------------------------------
__global__ void k_scan() {
    int idx = blockIdx.x * blockDim.x + threadIdx.x;
    if (idx >= BB * NCHUNK * DIM) return;
    int d  = idx & (DIM - 1);
    int nc = (idx >> 11) & (NCHUNK - 1);
    int b  = idx >> 15;

    size_t rowbase = (size_t)b * SEQ + nc * CHUNKL;
    const float* la = g_fused + rowbase * F3 + d;
    const float* vv = g_fused + rowbase * F3 + DIM + d;
    float*       ot = g_final + rowbase * DIM + d;

    float Ls = 0.f, Lmax = -1e30f;
    for (int i = 0; i < CHUNKL; i++) {
        Ls += la[(size_t)i * F3];
        float L = fminf(fmaxf(Ls, -20.f), 0.f);
        Lmax = fmaxf(Lmax, L);
    }
    Ls = 0.f;
    float sum = 0.f, lastL = 0.f, lastO = 0.f;
    for (int i = 0; i < CHUNKL; i++) {
        Ls += la[(size_t)i * F3];
        float L  = fminf(fmaxf(Ls, -20.f), 0.f);
        float Lt = L - Lmax;
        sum += expf(-Lt) * vv[(size_t)i * F3];
        float o = expf(Lt) * sum;
        ot[(size_t)i * DIM] = o;
        lastL = L; lastO = o;
    }
    g_bd[idx] = lastL;
    g_bo[idx] = lastO;
}

// ---------------- 6. cross-chunk carry scan --------------------------------
__global__ void k_carry() {
    int idx = blockIdx.x * blockDim.x + threadIdx.x;
    if (idx >= BB * DIM) return;
    int d = idx & (DIM - 1);
    int b = idx >> 11;

    float cd[NCHUNK];
    float run = 0.f, stab = -1e30f;
    #pragma unroll
    for (int nc = 0; nc < NCHUNK; nc++) {
        run += g_bd[(b * NCHUNK + nc) * DIM + d];
        float c = fminf(fmaxf(run, -80.f), 0.f);
        cd[nc] = c;
        stab = fmaxf(stab, c);
    }
    float acc = 0.f;
    #pragma unroll
    for (int nc = 0; nc < NCHUNK; nc++) {
        float ncd = fminf(fmaxf(cd[nc] - stab, -20.f), 0.f);
        g_carry[(b * NCHUNK + nc) * DIM + d] = acc * expf(ncd);
        acc += g_bo[(b * NCHUNK + nc) * DIM + d] * expf(-ncd);
    }
}

// ---------------- 7. apply carries: final += carry * exp(L) ----------------
__global__ void k_final() {
    int idx = blockIdx.x * blockDim.x + threadIdx.x;
    if (idx >= BB * NCHUNK * DIM) return;
    int d  = idx & (DIM - 1);
    int nc = (idx >> 11) & (NCHUNK - 1);
    int b  = idx >> 15;

    float carry = g_carry[idx];
    size_t rowbase = (size_t)b * SEQ + nc * CHUNKL;
    const float* la = g_fused + rowbase * F3 + d;
    float*       ot = g_final + rowbase * DIM + d;

    float Ls = 0.f;
    for (int i = 0; i < CHUNKL; i++) {
        Ls += la[(size_t)i * F3];
        float L = fminf(fmaxf(Ls, -20.f), 0.f);
        ot[(size_t)i * DIM] += carry * expf(L);
    }
}

// ---------------- 8. head mix + gate, emit fp16 A --------------------------
__global__ void k_mix(const float* __restrict__ head_mix) {
    int row = blockIdx.x;
    __shared__ float sf[DIM];
    __shared__ float hm[NH * NH];
    const float* fr = g_final + (size_t)row * DIM;
    const float* gr = g_fused + (size_t)row * F3 + 2 * DIM;

    for (int i = threadIdx.x; i < DIM; i += blockDim.x) sf[i] = fr[i];
    for (int i = threadIdx.x; i < NH * NH; i += blockDim.x) hm[i] = head_mix[i];
    __syncthreads();

    for (int i = threadIdx.x; i < DIM; i += blockDim.x) {
        int dd = i & (DHEAD - 1);
        int m  = i >> 7;
        float acc = 0.f;
        #pragma unroll
        for (int h = 0; h < NH; h++) acc += sf[h * DHEAD + dd] * hm[h * NH + m];
        float y = acc * gr[i];
        g_a16[(size_t)row * DIM + i] = __float2half_rn(y);
    }
}

// ---------------- launcher --------------------------------------------------
extern "C" void kernel_launch(void* const* d_in, const int* in_sizes, int n_in,
                              void* d_out, int out_size) {
    const float* x          = (const float*)d_in[0];
    const float* norm_scale = (const float*)d_in[1];
    const float* conv_w     = (const float*)d_in[2];
    const float* conv_b     = (const float*)d_in[3];
    const float* in_proj_w  = (const float*)d_in[4];
    const float* dt_bias    = (const float*)d_in[5];
    const float* head_mix   = (const float*)d_in[6];
    const float* out_proj_w = (const float*)d_in[7];
    float* out = (float*)d_out;

    float *p_fused;
    __half *p_a16, *p_b1, *p_b2;
    cudaGetSymbolAddress((void**)&p_fused, g_fused);
    cudaGetSymbolAddress((void**)&p_a16, g_a16);
    cudaGetSymbolAddress((void**)&p_b1, g_b1_16);
    cudaGetSymbolAddress((void**)&p_b2, g_b2_16);

    cudaFuncSetAttribute(k_gemm_mma, cudaFuncAttributeMaxDynamicSharedMemorySize,
                         SMEM_GEMM);

    k_rmsnorm<<<NROWS, 256>>>(x, norm_scale);
    k_conv<<<(NROWS * DIM) / 256, 256>>>(conv_w, conv_b);
    k_cvt16<<<(F3 * DIM / 4) / 256, 256>>>(in_proj_w, p_b1, F3 * DIM / 4);
    k_cvt16<<<(DIM * DIM / 4) / 256, 256>>>(out_proj_w, p_b2, DIM * DIM / 4);

    // fused = xc @ in_proj_w^T : M=8192, N=6144, K=2048
    k_gemm_mma<<<dim3(F3 / 128, NROWS / 128), 256, SMEM_GEMM>>>(
        p_a16, p_b1, p_fused, (const float*)0, F3, DIM);

    k_post<<<(NROWS * NH * DHALF) / 256, 256>>>(dt_bias);
    k_scan<<<(BB * NCHUNK * DIM) / 256, 256>>>();
    k_carry<<<(BB * DIM + 255) / 256, 256>>>();
    k_final<<<(BB * NCHUNK * DIM) / 256, 256>>>();
    k_mix<<<NROWS, 256>>>(head_mix);

    // out = residual + (vm*gate) @ out_proj_w^T : M=8192, N=2048, K=2048
    k_gemm_mma<<<dim3(DIM / 128, NROWS / 128), 256, SMEM_GEMM>>>(
        p_a16, p_b2, out, x, DIM, DIM);
}